// round 1
// baseline (speedup 1.0000x reference)
#include <cuda_runtime.h>
#include <math.h>

#define SEQ   2048
#define EMB   512
#define HEADS 8
#define HDIM  64
#define BATCH 2
#define MTOT  (BATCH * SEQ)   // 4096

// ---------------- scratch (static device globals; no allocation) ----------------
__device__ float g_Q [MTOT * EMB];
__device__ float g_K [MTOT * EMB];
__device__ float g_V [MTOT * EMB];
__device__ float g_G [MTOT * EMB];
__device__ float g_X2[MTOT * EMB];
__device__ float g_sin[SEQ * 32];
__device__ float g_cos[SEQ * 32];

// ---------------- rotary tables (double precision, tiny) ----------------
__global__ void rotary_table_kernel() {
    int idx = blockIdx.x * blockDim.x + threadIdx.x;
    if (idx >= SEQ * 32) return;
    int n = idx >> 5;
    int i = idx & 31;
    double t     = (double)i / 31.0;
    double theta = pow(10000.0, -t);
    double ang   = (double)n * theta;
    g_sin[idx] = (float)sin(ang);
    g_cos[idx] = (float)cos(ang);
}

// ---------------- tiled fp32 GEMM: C[M,512] = X[M,512] @ W[512,512]^T ----------------
// BM=128, BN=128, BK=16, 256 threads, 8x8 microtile.
// modes: 0 = +bias ; 1 = +bias,rotary ; 2 = +bias,rotary,*0.125 ; 3 = +bias,silu
__device__ __forceinline__ void gemm_tile(
    const float* __restrict__ X, const float* __restrict__ W,
    const float* __restrict__ bias, float* __restrict__ C, int mode)
{
    __shared__ float As[16][128];
    __shared__ float Bs[16][128];
    const int tid = threadIdx.x;
    const int tx  = tid & 15;
    const int ty  = tid >> 4;
    const int m0  = blockIdx.y * 128;
    const int n0  = blockIdx.x * 128;

    const int lrow = tid >> 1;          // 0..127
    const int lc0  = (tid & 1) * 2;     // float4-pair base: 0 or 2

    const float* Xp = X + (size_t)(m0 + lrow) * EMB + lc0 * 4;
    const float* Wp = W + (size_t)(n0 + lrow) * EMB + lc0 * 4;

    float acc[8][8];
    #pragma unroll
    for (int i = 0; i < 8; i++)
        #pragma unroll
        for (int j = 0; j < 8; j++) acc[i][j] = 0.f;

    for (int k0 = 0; k0 < EMB; k0 += 16) {
        float4 xa = *(const float4*)(Xp + k0);
        float4 xb = *(const float4*)(Xp + k0 + 4);
        float4 wa = *(const float4*)(Wp + k0);
        float4 wb = *(const float4*)(Wp + k0 + 4);
        __syncthreads();
        As[lc0*4+0][lrow] = xa.x; As[lc0*4+1][lrow] = xa.y;
        As[lc0*4+2][lrow] = xa.z; As[lc0*4+3][lrow] = xa.w;
        As[lc0*4+4][lrow] = xb.x; As[lc0*4+5][lrow] = xb.y;
        As[lc0*4+6][lrow] = xb.z; As[lc0*4+7][lrow] = xb.w;
        Bs[lc0*4+0][lrow] = wa.x; Bs[lc0*4+1][lrow] = wa.y;
        Bs[lc0*4+2][lrow] = wa.z; Bs[lc0*4+3][lrow] = wa.w;
        Bs[lc0*4+4][lrow] = wb.x; Bs[lc0*4+5][lrow] = wb.y;
        Bs[lc0*4+6][lrow] = wb.z; Bs[lc0*4+7][lrow] = wb.w;
        __syncthreads();

        #pragma unroll
        for (int kk = 0; kk < 16; kk++) {
            float4 a0 = *(const float4*)&As[kk][ty*8];
            float4 a1 = *(const float4*)&As[kk][ty*8+4];
            float4 b0 = *(const float4*)&Bs[kk][tx*8];
            float4 b1 = *(const float4*)&Bs[kk][tx*8+4];
            float av[8] = {a0.x,a0.y,a0.z,a0.w,a1.x,a1.y,a1.z,a1.w};
            float bv[8] = {b0.x,b0.y,b0.z,b0.w,b1.x,b1.y,b1.z,b1.w};
            #pragma unroll
            for (int i = 0; i < 8; i++)
                #pragma unroll
                for (int j = 0; j < 8; j++)
                    acc[i][j] = fmaf(av[i], bv[j], acc[i][j]);
        }
    }

    // epilogue
    #pragma unroll
    for (int i = 0; i < 8; i++) {
        int row = m0 + ty*8 + i;
        int n   = row & (SEQ - 1);
        float v[8];
        #pragma unroll
        for (int j = 0; j < 8; j++) v[j] = acc[i][j] + bias[n0 + tx*8 + j];

        if (mode == 1 || mode == 2) {
            #pragma unroll
            for (int j = 0; j < 8; j += 2) {
                int col = n0 + tx*8 + j;
                int d   = col & 63;
                float s = g_sin[n*32 + (d >> 1)];
                float c = g_cos[n*32 + (d >> 1)];
                float e = v[j], o = v[j+1];
                v[j]   = e*c - o*s;
                v[j+1] = o*c + e*s;
            }
            if (mode == 2) {
                #pragma unroll
                for (int j = 0; j < 8; j++) v[j] *= 0.125f;  // 1/sqrt(64)
            }
        } else if (mode == 3) {
            #pragma unroll
            for (int j = 0; j < 8; j++) v[j] = v[j] / (1.f + expf(-v[j]));
        }

        float* cp = C + (size_t)row * EMB + n0 + tx*8;
        *(float4*)(cp)     = make_float4(v[0], v[1], v[2], v[3]);
        *(float4*)(cp + 4) = make_float4(v[4], v[5], v[6], v[7]);
    }
}

__global__ void __launch_bounds__(256) proj_kernel(
    const float* __restrict__ q_in, const float* __restrict__ k_in,
    const float* __restrict__ v_in,
    const float* __restrict__ Wq, const float* __restrict__ bq,
    const float* __restrict__ Wk, const float* __restrict__ bk,
    const float* __restrict__ Wv, const float* __restrict__ bv,
    const float* __restrict__ Wg, const float* __restrict__ bg)
{
    int job = blockIdx.z;
    const float* X; const float* W; const float* B; float* O; int mode;
    if      (job == 0) { X = q_in; W = Wq; B = bq; O = g_Q; mode = 1; }
    else if (job == 1) { X = k_in; W = Wk; B = bk; O = g_K; mode = 2; }
    else if (job == 2) { X = v_in; W = Wv; B = bv; O = g_V; mode = 0; }
    else               { X = q_in; W = Wg; B = bg; O = g_G; mode = 3; }
    gemm_tile(X, W, B, O, mode);
}

__global__ void __launch_bounds__(256) out_kernel(
    const float* __restrict__ Wo, const float* __restrict__ bo,
    float* __restrict__ out)
{
    gemm_tile(g_X2, Wo, bo, out, 0);
}

// ---------------- retention: causal decay attention + fused GroupNorm*gate ----------------
// grid: (qtile 0..31, head 0..7, batch 0..1), 256 threads.
// Per block: Q tile [64q x 64d], stream key tiles [64s x 64d], O in registers,
// then GroupNorm over d and gate multiply, write g_X2 in [b,n,h*64+d] layout.
__global__ void __launch_bounds__(256) retention_kernel()
{
    __shared__ float QsT[64 * 64];   // [d][q]
    __shared__ float KSs[64 * 64];   // K^T [d][s] -> S^T [s][q] -> O [q][d]
    __shared__ float Vss[64 * 64];   // [s][d]

    const int tid = threadIdx.x;
    const int tx  = tid & 15;
    const int ty  = tid >> 4;
    const int qt  = blockIdx.x;          // 0..31
    const int h   = blockIdx.y;
    const int b   = blockIdx.z;
    const int qbase   = qt * 64;
    const int rowbase = b * SEQ;
    const int coff    = h * HDIM;

    // per-head gamma (computed in double for safety)
    const double l0 = log(1.0 / 32.0), l1 = log(1.0 / 512.0);
    const double gd = 1.0 - exp(l0 + (double)h * (l1 - l0) / 7.0);
    const float  gamma = (float)gd;
    const float  lg    = (float)log(gd);
    float gi[4], gjv[4];
    gi[0]  = 1.f; gi[1]  = gamma;      gi[2]  = gamma * gamma;   gi[3]  = gi[2] * gamma;
    float ginv = 1.f / gamma;
    gjv[0] = 1.f; gjv[1] = ginv;       gjv[2] = ginv * ginv;     gjv[3] = gjv[2] * ginv;

    // load Q tile transposed: QsT[d][q]
    for (int f = tid; f < 1024; f += 256) {
        int s  = f & 63;
        int d4 = f >> 6;                 // 0..15
        float4 qv = *(const float4*)&g_Q[(size_t)(rowbase + qbase + s) * EMB + coff + d4*4];
        QsT[(d4*4+0)*64 + s] = qv.x;
        QsT[(d4*4+1)*64 + s] = qv.y;
        QsT[(d4*4+2)*64 + s] = qv.z;
        QsT[(d4*4+3)*64 + s] = qv.w;
    }

    float oacc[4][4];
    #pragma unroll
    for (int i = 0; i < 4; i++)
        #pragma unroll
        for (int j = 0; j < 4; j++) oacc[i][j] = 0.f;

    for (int t = 0; t <= qt; ++t) {
        const int sbase = t * 64;
        __syncthreads();   // protect KSs/Vss from previous iteration's readers (also fences QsT stores on t==0)
        for (int f = tid; f < 1024; f += 256) {
            int s  = f & 63;
            int d4 = f >> 6;
            size_t gidx = (size_t)(rowbase + sbase + s) * EMB + coff + d4*4;
            float4 kv = *(const float4*)&g_K[gidx];
            KSs[(d4*4+0)*64 + s] = kv.x;
            KSs[(d4*4+1)*64 + s] = kv.y;
            KSs[(d4*4+2)*64 + s] = kv.z;
            KSs[(d4*4+3)*64 + s] = kv.w;
            float4 vv = *(const float4*)&g_V[gidx];
            *(float4*)&Vss[s*64 + d4*4] = vv;
        }
        __syncthreads();

        // GEMM1: S[q][s] = sum_d QsT[d][q] * KsT[d][s]
        float sacc[4][4];
        #pragma unroll
        for (int i = 0; i < 4; i++)
            #pragma unroll
            for (int j = 0; j < 4; j++) sacc[i][j] = 0.f;
        #pragma unroll
        for (int d = 0; d < 64; d++) {
            float4 a = *(const float4*)&QsT[d*64 + ty*4];
            float4 bb = *(const float4*)&KSs[d*64 + tx*4];
            float av[4] = {a.x, a.y, a.z, a.w};
            float bv[4] = {bb.x, bb.y, bb.z, bb.w};
            #pragma unroll
            for (int i = 0; i < 4; i++)
                #pragma unroll
                for (int j = 0; j < 4; j++)
                    sacc[i][j] = fmaf(av[i], bv[j], sacc[i][j]);
        }

        // decay: gamma^(n - s) = d0 * gamma^i * gamma^-j ; mask only on diagonal tile
        float d0 = expf(lg * (float)((qbase + ty*4) - (sbase + tx*4)));
        if (t == qt) {
            #pragma unroll
            for (int i = 0; i < 4; i++) {
                int n = ty*4 + i;
                #pragma unroll
                for (int j = 0; j < 4; j++) {
                    int s = tx*4 + j;
                    sacc[i][j] = (s <= n) ? sacc[i][j] * d0 * gi[i] * gjv[j] : 0.f;
                }
            }
        } else {
            #pragma unroll
            for (int i = 0; i < 4; i++)
                #pragma unroll
                for (int j = 0; j < 4; j++)
                    sacc[i][j] *= d0 * gi[i] * gjv[j];
        }

        __syncthreads();   // all GEMM1 reads of KSs done
        // store S transposed: SsT[s][q]
        #pragma unroll
        for (int j = 0; j < 4; j++) {
            *(float4*)&KSs[(tx*4+j)*64 + ty*4] =
                make_float4(sacc[0][j], sacc[1][j], sacc[2][j], sacc[3][j]);
        }
        __syncthreads();

        // GEMM2: O[q][d] += sum_s SsT[s][q] * Vs[s][d]
        #pragma unroll
        for (int s = 0; s < 64; s++) {
            float4 a = *(const float4*)&KSs[s*64 + ty*4];
            float4 bb = *(const float4*)&Vss[s*64 + tx*4];
            float av[4] = {a.x, a.y, a.z, a.w};
            float bv[4] = {bb.x, bb.y, bb.z, bb.w};
            #pragma unroll
            for (int i = 0; i < 4; i++)
                #pragma unroll
                for (int j = 0; j < 4; j++)
                    oacc[i][j] = fmaf(av[i], bv[j], oacc[i][j]);
        }
    }

    // stage O[q][d] into smem (reuse KSs)
    __syncthreads();
    #pragma unroll
    for (int i = 0; i < 4; i++)
        *(float4*)&KSs[(ty*4+i)*64 + tx*4] =
            make_float4(oacc[i][0], oacc[i][1], oacc[i][2], oacc[i][3]);
    __syncthreads();

    // GroupNorm over d (per q row) + SiLU-gate multiply; 4 threads per row
    const int r = tid >> 2;      // row 0..63
    const int p = tid & 3;       // quarter 0..3
    float vals[16];
    float lsum = 0.f;
    #pragma unroll
    for (int j = 0; j < 16; j++) {
        vals[j] = KSs[r*64 + p*16 + j];
        lsum += vals[j];
    }
    lsum += __shfl_xor_sync(0xffffffffu, lsum, 1);
    lsum += __shfl_xor_sync(0xffffffffu, lsum, 2);
    float mean = lsum * (1.f / 64.f);
    float lsq = 0.f;
    #pragma unroll
    for (int j = 0; j < 16; j++) {
        float dd = vals[j] - mean;
        lsq += dd * dd;
    }
    lsq += __shfl_xor_sync(0xffffffffu, lsq, 1);
    lsq += __shfl_xor_sync(0xffffffffu, lsq, 2);
    float rstd = rsqrtf(lsq * (1.f / 64.f) + 1e-6f);

    const int n = qbase + r;
    const size_t gidx = (size_t)(rowbase + n) * EMB + coff + p*16;
    #pragma unroll
    for (int j = 0; j < 16; j += 4) {
        float4 g = *(const float4*)&g_G[gidx + j];
        float4 o;
        o.x = (vals[j+0] - mean) * rstd * g.x;
        o.y = (vals[j+1] - mean) * rstd * g.y;
        o.z = (vals[j+2] - mean) * rstd * g.z;
        o.w = (vals[j+3] - mean) * rstd * g.w;
        *(float4*)&g_X2[gidx + j] = o;
    }
}

// ---------------- launch ----------------
extern "C" void kernel_launch(void* const* d_in, const int* in_sizes, int n_in,
                              void* d_out, int out_size)
{
    const float* query = (const float*)d_in[0];
    const float* kk    = (const float*)d_in[1];
    const float* vv    = (const float*)d_in[2];
    const float* Wq    = (const float*)d_in[3];
    const float* bq    = (const float*)d_in[4];
    const float* Wk    = (const float*)d_in[5];
    const float* bk    = (const float*)d_in[6];
    const float* Wv    = (const float*)d_in[7];
    const float* bv    = (const float*)d_in[8];
    const float* Wg    = (const float*)d_in[9];
    const float* bg    = (const float*)d_in[10];
    const float* Wo    = (const float*)d_in[11];
    const float* bo    = (const float*)d_in[12];
    float* out = (float*)d_out;

    rotary_table_kernel<<<(SEQ*32 + 255) / 256, 256>>>();

    dim3 pg(4, 32, 4);              // n-tiles, m-tiles, jobs(Q,K,V,G)
    proj_kernel<<<pg, 256>>>(query, kk, vv, Wq, bq, Wk, bk, Wv, bv, Wg, bg);

    dim3 rg(32, 8, 2);              // q-tiles, heads, batch
    retention_kernel<<<rg, 256>>>();

    dim3 og(4, 32, 1);
    out_kernel<<<og, 256>>>(Wo, bo, out);
}

// round 2
// speedup vs baseline: 1.9128x; 1.9128x over previous
#include <cuda_runtime.h>
#include <math.h>

#define SEQ   2048
#define EMB   512
#define HEADS 8
#define HDIM  64
#define BATCH 2
#define MTOT  (BATCH * SEQ)   // 4096
#define CHUNK 64
#define NCH   (SEQ / CHUNK)   // 32
#define NBH   (BATCH * HEADS) // 16

// ---------------- scratch (static device globals; no allocation) ----------------
__device__ float g_Q [MTOT * EMB];
__device__ float g_K [MTOT * EMB];
__device__ float g_V [MTOT * EMB];
__device__ float g_G [MTOT * EMB];
__device__ float g_X2[MTOT * EMB];
__device__ float g_A [NBH * NCH * HDIM * HDIM];   // per-chunk K'^T V   (8 MB)
__device__ float g_S [NBH * NCH * HDIM * HDIM];   // scanned states     (8 MB)
__device__ float g_sin[SEQ * 32];
__device__ float g_cos[SEQ * 32];

// ---------------- rotary tables (double precision, tiny) ----------------
__global__ void rotary_table_kernel() {
    int idx = blockIdx.x * blockDim.x + threadIdx.x;
    if (idx >= SEQ * 32) return;
    int n = idx >> 5;
    int i = idx & 31;
    double t     = (double)i / 31.0;
    double theta = pow(10000.0, -t);
    double ang   = (double)n * theta;
    g_sin[idx] = (float)sin(ang);
    g_cos[idx] = (float)cos(ang);
}

__device__ __forceinline__ double head_gamma(int h) {
    const double l0 = log(1.0 / 32.0), l1 = log(1.0 / 512.0);
    return 1.0 - exp(l0 + (double)h * (l1 - l0) / 7.0);
}

// ---------------- tiled fp32 GEMM: C[M,512] = X[M,512] @ W[512,512]^T ----------------
// BM=128, BN=128, BK=16, 256 threads, 8x8 microtile.
// modes: 0 = +bias ; 1 = +bias,rotary ; 2 = +bias,rotary,*0.125 ; 3 = +bias,silu
__device__ __forceinline__ void gemm_tile(
    const float* __restrict__ X, const float* __restrict__ W,
    const float* __restrict__ bias, float* __restrict__ C, int mode)
{
    __shared__ float As[16][128];
    __shared__ float Bs[16][128];
    const int tid = threadIdx.x;
    const int tx  = tid & 15;
    const int ty  = tid >> 4;
    const int m0  = blockIdx.y * 128;
    const int n0  = blockIdx.x * 128;

    const int lrow = tid >> 1;          // 0..127
    const int lc0  = (tid & 1) * 2;     // float4-pair base: 0 or 2

    const float* Xp = X + (size_t)(m0 + lrow) * EMB + lc0 * 4;
    const float* Wp = W + (size_t)(n0 + lrow) * EMB + lc0 * 4;

    float acc[8][8];
    #pragma unroll
    for (int i = 0; i < 8; i++)
        #pragma unroll
        for (int j = 0; j < 8; j++) acc[i][j] = 0.f;

    for (int k0 = 0; k0 < EMB; k0 += 16) {
        float4 xa = *(const float4*)(Xp + k0);
        float4 xb = *(const float4*)(Xp + k0 + 4);
        float4 wa = *(const float4*)(Wp + k0);
        float4 wb = *(const float4*)(Wp + k0 + 4);
        __syncthreads();
        As[lc0*4+0][lrow] = xa.x; As[lc0*4+1][lrow] = xa.y;
        As[lc0*4+2][lrow] = xa.z; As[lc0*4+3][lrow] = xa.w;
        As[lc0*4+4][lrow] = xb.x; As[lc0*4+5][lrow] = xb.y;
        As[lc0*4+6][lrow] = xb.z; As[lc0*4+7][lrow] = xb.w;
        Bs[lc0*4+0][lrow] = wa.x; Bs[lc0*4+1][lrow] = wa.y;
        Bs[lc0*4+2][lrow] = wa.z; Bs[lc0*4+3][lrow] = wa.w;
        Bs[lc0*4+4][lrow] = wb.x; Bs[lc0*4+5][lrow] = wb.y;
        Bs[lc0*4+6][lrow] = wb.z; Bs[lc0*4+7][lrow] = wb.w;
        __syncthreads();

        #pragma unroll
        for (int kk = 0; kk < 16; kk++) {
            float4 a0 = *(const float4*)&As[kk][ty*8];
            float4 a1 = *(const float4*)&As[kk][ty*8+4];
            float4 b0 = *(const float4*)&Bs[kk][tx*8];
            float4 b1 = *(const float4*)&Bs[kk][tx*8+4];
            float av[8] = {a0.x,a0.y,a0.z,a0.w,a1.x,a1.y,a1.z,a1.w};
            float bv[8] = {b0.x,b0.y,b0.z,b0.w,b1.x,b1.y,b1.z,b1.w};
            #pragma unroll
            for (int i = 0; i < 8; i++)
                #pragma unroll
                for (int j = 0; j < 8; j++)
                    acc[i][j] = fmaf(av[i], bv[j], acc[i][j]);
        }
    }

    // epilogue
    #pragma unroll
    for (int i = 0; i < 8; i++) {
        int row = m0 + ty*8 + i;
        int n   = row & (SEQ - 1);
        float v[8];
        #pragma unroll
        for (int j = 0; j < 8; j++) v[j] = acc[i][j] + bias[n0 + tx*8 + j];

        if (mode == 1 || mode == 2) {
            #pragma unroll
            for (int j = 0; j < 8; j += 2) {
                int col = n0 + tx*8 + j;
                int d   = col & 63;
                float s = g_sin[n*32 + (d >> 1)];
                float c = g_cos[n*32 + (d >> 1)];
                float e = v[j], o = v[j+1];
                v[j]   = e*c - o*s;
                v[j+1] = o*c + e*s;
            }
            if (mode == 2) {
                #pragma unroll
                for (int j = 0; j < 8; j++) v[j] *= 0.125f;  // 1/sqrt(64)
            }
        } else if (mode == 3) {
            #pragma unroll
            for (int j = 0; j < 8; j++) v[j] = v[j] / (1.f + expf(-v[j]));
        }

        float* cp = C + (size_t)row * EMB + n0 + tx*8;
        *(float4*)(cp)     = make_float4(v[0], v[1], v[2], v[3]);
        *(float4*)(cp + 4) = make_float4(v[4], v[5], v[6], v[7]);
    }
}

__global__ void __launch_bounds__(256) proj_kernel(
    const float* __restrict__ q_in, const float* __restrict__ k_in,
    const float* __restrict__ v_in,
    const float* __restrict__ Wq, const float* __restrict__ bq,
    const float* __restrict__ Wk, const float* __restrict__ bk,
    const float* __restrict__ Wv, const float* __restrict__ bv,
    const float* __restrict__ Wg, const float* __restrict__ bg)
{
    int job = blockIdx.z;
    const float* X; const float* W; const float* B; float* O; int mode;
    if      (job == 0) { X = q_in; W = Wq; B = bq; O = g_Q; mode = 1; }
    else if (job == 1) { X = k_in; W = Wk; B = bk; O = g_K; mode = 2; }
    else if (job == 2) { X = v_in; W = Wv; B = bv; O = g_V; mode = 0; }
    else               { X = q_in; W = Wg; B = bg; O = g_G; mode = 3; }
    gemm_tile(X, W, B, O, mode);
}

__global__ void __launch_bounds__(256) out_kernel(
    const float* __restrict__ Wo, const float* __restrict__ bo,
    float* __restrict__ out)
{
    gemm_tile(g_X2, Wo, bo, out, 0);
}

// ================= chunkwise retention =================
// R1: per-chunk A = (K * gamma^(C-j))^T V   [64 x 64], K-dim = 64
// grid: (chunk 0..31, head, batch), 256 threads, 16x16 x (4x4 microtile)
__global__ void __launch_bounds__(256) chunk_kv_kernel()
{
    __shared__ float Ks[CHUNK * HDIM];  // [s][d], pre-scaled
    __shared__ float Vs[CHUNK * HDIM];  // [s][d]

    const int tid = threadIdx.x;
    const int tx  = tid & 15;
    const int ty  = tid >> 4;
    const int c   = blockIdx.x;
    const int h   = blockIdx.y;
    const int b   = blockIdx.z;
    const int rowbase = b * SEQ + c * CHUNK;
    const int coff    = h * HDIM;

    const double gd = head_gamma(h);
    const float  lg = (float)log(gd);

    for (int f = tid; f < CHUNK * 16; f += 256) {
        int s  = f >> 4;       // 0..63
        int d4 = f & 15;       // 0..15
        size_t gidx = (size_t)(rowbase + s) * EMB + coff + d4*4;
        float sc = expf(lg * (float)(CHUNK - s));
        float4 kv = *(const float4*)&g_K[gidx];
        kv.x *= sc; kv.y *= sc; kv.z *= sc; kv.w *= sc;
        *(float4*)&Ks[s*HDIM + d4*4] = kv;
        *(float4*)&Vs[s*HDIM + d4*4] = *(const float4*)&g_V[gidx];
    }
    __syncthreads();

    float acc[4][4];
    #pragma unroll
    for (int i = 0; i < 4; i++)
        #pragma unroll
        for (int j = 0; j < 4; j++) acc[i][j] = 0.f;

    #pragma unroll 8
    for (int s = 0; s < CHUNK; s++) {
        float4 a = *(const float4*)&Ks[s*HDIM + ty*4];   // A rows = dk
        float4 bb = *(const float4*)&Vs[s*HDIM + tx*4];  // A cols = dv
        float av[4] = {a.x, a.y, a.z, a.w};
        float bv[4] = {bb.x, bb.y, bb.z, bb.w};
        #pragma unroll
        for (int i = 0; i < 4; i++)
            #pragma unroll
            for (int j = 0; j < 4; j++)
                acc[i][j] = fmaf(av[i], bv[j], acc[i][j]);
    }

    float* Ap = g_A + (size_t)(((b*HEADS + h)*NCH + c) * HDIM * HDIM);
    #pragma unroll
    for (int i = 0; i < 4; i++)
        *(float4*)&Ap[(ty*4+i)*HDIM + tx*4] =
            make_float4(acc[i][0], acc[i][1], acc[i][2], acc[i][3]);
}

// R2: elementwise scan over chunks: S_t = gamma^C * S_{t-1} + A_{t-1}; S_0 = 0.
// grid: (bh 0..15, seg 0..15), 256 threads; each thread owns one state element.
__global__ void __launch_bounds__(256) state_scan_kernel()
{
    const int bh  = blockIdx.x;
    const int seg = blockIdx.y;
    const int e   = seg * 256 + threadIdx.x;   // 0..4095
    const int h   = bh & (HEADS - 1);
    const float gc = (float)pow(head_gamma(h), (double)CHUNK);

    const size_t base = (size_t)bh * NCH * HDIM * HDIM + e;
    float s = 0.f;
    #pragma unroll 4
    for (int t = 0; t < NCH; t++) {
        g_S[base + (size_t)t * HDIM * HDIM] = s;
        s = gc * s + g_A[base + (size_t)t * HDIM * HDIM];
    }
}

// R3: intra-chunk (diagonal decay tile) + cross term via state, fused GroupNorm*gate.
// grid: (chunk, head, batch), 256 threads, 16x16 x (4x4 microtile)
__global__ void __launch_bounds__(256) retention_kernel()
{
    __shared__ float QsT[HDIM * CHUNK];  // [d][q]
    __shared__ float KsT[HDIM * CHUNK];  // [d][s] -> S^T [s][q] -> O [q][d]
    __shared__ float Vs [CHUNK * HDIM];  // [s][d]
    __shared__ float Ss [HDIM * HDIM];   // state [dk][dv]

    const int tid = threadIdx.x;
    const int tx  = tid & 15;
    const int ty  = tid >> 4;
    const int c   = blockIdx.x;
    const int h   = blockIdx.y;
    const int b   = blockIdx.z;
    const int rowbase = b * SEQ + c * CHUNK;
    const int coff    = h * HDIM;

    const double gd = head_gamma(h);
    const float  gamma = (float)gd;
    const float  lg    = (float)log(gd);
    float gi[4], gjv[4];
    gi[0]  = 1.f; gi[1] = gamma; gi[2] = gamma*gamma; gi[3] = gi[2]*gamma;
    float ginv = 1.f / gamma;
    gjv[0] = 1.f; gjv[1] = ginv; gjv[2] = ginv*ginv;  gjv[3] = gjv[2]*ginv;

    // loads
    const float* Sp = g_S + (size_t)(((b*HEADS + h)*NCH + c) * HDIM * HDIM);
    for (int f = tid; f < CHUNK * 16; f += 256) {
        int s  = f & 63;
        int d4 = f >> 6;
        size_t gidx = (size_t)(rowbase + s) * EMB + coff + d4*4;
        float4 qv = *(const float4*)&g_Q[gidx];
        QsT[(d4*4+0)*CHUNK + s] = qv.x;
        QsT[(d4*4+1)*CHUNK + s] = qv.y;
        QsT[(d4*4+2)*CHUNK + s] = qv.z;
        QsT[(d4*4+3)*CHUNK + s] = qv.w;
        float4 kv = *(const float4*)&g_K[gidx];
        KsT[(d4*4+0)*CHUNK + s] = kv.x;
        KsT[(d4*4+1)*CHUNK + s] = kv.y;
        KsT[(d4*4+2)*CHUNK + s] = kv.z;
        KsT[(d4*4+3)*CHUNK + s] = kv.w;
        *(float4*)&Vs[s*HDIM + d4*4] = *(const float4*)&g_V[gidx];
        // state load (row-major copy): reuse f as element index
        *(float4*)&Ss[f*4] = *(const float4*)&Sp[f*4];
    }
    __syncthreads();

    // GEMM1 (intra): S[q][s] = sum_d QsT[d][q] * KsT[d][s], with decay + causal mask
    float sacc[4][4];
    #pragma unroll
    for (int i = 0; i < 4; i++)
        #pragma unroll
        for (int j = 0; j < 4; j++) sacc[i][j] = 0.f;
    #pragma unroll 8
    for (int d = 0; d < HDIM; d++) {
        float4 a  = *(const float4*)&QsT[d*CHUNK + ty*4];
        float4 bb = *(const float4*)&KsT[d*CHUNK + tx*4];
        float av[4] = {a.x, a.y, a.z, a.w};
        float bv[4] = {bb.x, bb.y, bb.z, bb.w};
        #pragma unroll
        for (int i = 0; i < 4; i++)
            #pragma unroll
            for (int j = 0; j < 4; j++)
                sacc[i][j] = fmaf(av[i], bv[j], sacc[i][j]);
    }
    {
        float d0 = expf(lg * (float)(ty*4 - tx*4));
        #pragma unroll
        for (int i = 0; i < 4; i++) {
            int n = ty*4 + i;
            #pragma unroll
            for (int j = 0; j < 4; j++) {
                int s = tx*4 + j;
                sacc[i][j] = (s <= n) ? sacc[i][j] * d0 * gi[i] * gjv[j] : 0.f;
            }
        }
    }
    __syncthreads();     // done reading KsT
    #pragma unroll
    for (int j = 0; j < 4; j++)
        *(float4*)&KsT[(tx*4+j)*CHUNK + ty*4] =
            make_float4(sacc[0][j], sacc[1][j], sacc[2][j], sacc[3][j]);
    __syncthreads();

    // GEMM2: O[q][d] = sum_s SsT[s][q] * Vs[s][d]
    float oacc[4][4];
    #pragma unroll
    for (int i = 0; i < 4; i++)
        #pragma unroll
        for (int j = 0; j < 4; j++) oacc[i][j] = 0.f;
    #pragma unroll 8
    for (int s = 0; s < CHUNK; s++) {
        float4 a  = *(const float4*)&KsT[s*CHUNK + ty*4];
        float4 bb = *(const float4*)&Vs[s*HDIM + tx*4];
        float av[4] = {a.x, a.y, a.z, a.w};
        float bv[4] = {bb.x, bb.y, bb.z, bb.w};
        #pragma unroll
        for (int i = 0; i < 4; i++)
            #pragma unroll
            for (int j = 0; j < 4; j++)
                oacc[i][j] = fmaf(av[i], bv[j], oacc[i][j]);
    }

    // GEMM3 (cross): O[q=i][dv] += gamma^i * sum_dk Q[i][dk] * S[dk][dv]
    {
        float cacc[4][4];
        #pragma unroll
        for (int i = 0; i < 4; i++)
            #pragma unroll
            for (int j = 0; j < 4; j++) cacc[i][j] = 0.f;
        #pragma unroll 8
        for (int d = 0; d < HDIM; d++) {
            float4 a  = *(const float4*)&QsT[d*CHUNK + ty*4];
            float4 bb = *(const float4*)&Ss[d*HDIM + tx*4];
            float av[4] = {a.x, a.y, a.z, a.w};
            float bv[4] = {bb.x, bb.y, bb.z, bb.w};
            #pragma unroll
            for (int i = 0; i < 4; i++)
                #pragma unroll
                for (int j = 0; j < 4; j++)
                    cacc[i][j] = fmaf(av[i], bv[j], cacc[i][j]);
        }
        #pragma unroll
        for (int i = 0; i < 4; i++) {
            float gq = expf(lg * (float)(ty*4 + i));
            #pragma unroll
            for (int j = 0; j < 4; j++)
                oacc[i][j] = fmaf(gq, cacc[i][j], oacc[i][j]);
        }
    }

    // stage O[q][d] into smem (reuse KsT)
    __syncthreads();
    #pragma unroll
    for (int i = 0; i < 4; i++)
        *(float4*)&KsT[(ty*4+i)*HDIM + tx*4] =
            make_float4(oacc[i][0], oacc[i][1], oacc[i][2], oacc[i][3]);
    __syncthreads();

    // GroupNorm over d (per q row) + SiLU-gate multiply; 4 threads per row
    const int r = tid >> 2;      // row 0..63
    const int p = tid & 3;       // quarter 0..3
    float vals[16];
    float lsum = 0.f;
    #pragma unroll
    for (int j = 0; j < 16; j++) {
        vals[j] = KsT[r*HDIM + p*16 + j];
        lsum += vals[j];
    }
    lsum += __shfl_xor_sync(0xffffffffu, lsum, 1);
    lsum += __shfl_xor_sync(0xffffffffu, lsum, 2);
    float mean = lsum * (1.f / 64.f);
    float lsq = 0.f;
    #pragma unroll
    for (int j = 0; j < 16; j++) {
        float dd = vals[j] - mean;
        lsq += dd * dd;
    }
    lsq += __shfl_xor_sync(0xffffffffu, lsq, 1);
    lsq += __shfl_xor_sync(0xffffffffu, lsq, 2);
    float rstd = rsqrtf(lsq * (1.f / 64.f) + 1e-6f);

    const int n = c * CHUNK + r;
    const size_t gidx = (size_t)(b * SEQ + n) * EMB + coff + p*16;
    #pragma unroll
    for (int j = 0; j < 16; j += 4) {
        float4 g = *(const float4*)&g_G[gidx + j];
        float4 o;
        o.x = (vals[j+0] - mean) * rstd * g.x;
        o.y = (vals[j+1] - mean) * rstd * g.y;
        o.z = (vals[j+2] - mean) * rstd * g.z;
        o.w = (vals[j+3] - mean) * rstd * g.w;
        *(float4*)&g_X2[gidx + j] = o;
    }
}

// ---------------- launch ----------------
extern "C" void kernel_launch(void* const* d_in, const int* in_sizes, int n_in,
                              void* d_out, int out_size)
{
    const float* query = (const float*)d_in[0];
    const float* kk    = (const float*)d_in[1];
    const float* vv    = (const float*)d_in[2];
    const float* Wq    = (const float*)d_in[3];
    const float* bq    = (const float*)d_in[4];
    const float* Wk    = (const float*)d_in[5];
    const float* bk    = (const float*)d_in[6];
    const float* Wv    = (const float*)d_in[7];
    const float* bv    = (const float*)d_in[8];
    const float* Wg    = (const float*)d_in[9];
    const float* bg    = (const float*)d_in[10];
    const float* Wo    = (const float*)d_in[11];
    const float* bo    = (const float*)d_in[12];
    float* out = (float*)d_out;

    rotary_table_kernel<<<(SEQ*32 + 255) / 256, 256>>>();

    dim3 pg(4, 32, 4);              // n-tiles, m-tiles, jobs(Q,K,V,G)
    proj_kernel<<<pg, 256>>>(query, kk, vv, Wq, bq, Wk, bk, Wv, bv, Wg, bg);

    dim3 ag(NCH, HEADS, BATCH);     // per-chunk K'^T V
    chunk_kv_kernel<<<ag, 256>>>();

    dim3 sg(NBH, 16);               // state scan
    state_scan_kernel<<<sg, 256>>>();

    dim3 rg(NCH, HEADS, BATCH);     // intra + cross + GN + gate
    retention_kernel<<<rg, 256>>>();

    dim3 og(4, 32, 1);
    out_kernel<<<og, 256>>>(Wo, bo, out);
}

// round 3
// speedup vs baseline: 2.9569x; 1.5458x over previous
#include <cuda_runtime.h>
#include <math.h>
#include <stdint.h>

#define SEQ   2048
#define EMB   512
#define HEADS 8
#define HDIM  64
#define BATCH 2
#define MTOT  (BATCH * SEQ)   // 4096
#define CHUNK 64
#define NCH   (SEQ / CHUNK)   // 32
#define NBH   (BATCH * HEADS) // 16

// ---------------- scratch (static device globals; no allocation) ----------------
__device__ float g_Q [MTOT * EMB];
__device__ float g_K [MTOT * EMB];
__device__ float g_V [MTOT * EMB];
__device__ float g_G [MTOT * EMB];
__device__ float g_X2[MTOT * EMB];
__device__ float g_A [NBH * NCH * HDIM * HDIM];   // per-chunk K'^T V
__device__ float g_S [NBH * NCH * HDIM * HDIM];   // scanned states
__device__ float g_sin[SEQ * 32];
__device__ float g_cos[SEQ * 32];

// ---------------- rotary tables (double precision, tiny) ----------------
__global__ void rotary_table_kernel() {
    int idx = blockIdx.x * blockDim.x + threadIdx.x;
    if (idx >= SEQ * 32) return;
    int n = idx >> 5;
    int i = idx & 31;
    double t     = (double)i / 31.0;
    double theta = pow(10000.0, -t);
    double ang   = (double)n * theta;
    g_sin[idx] = (float)sin(ang);
    g_cos[idx] = (float)cos(ang);
}

__device__ __forceinline__ double head_gamma(int h) {
    const double l0 = log(1.0 / 32.0), l1 = log(1.0 / 512.0);
    return 1.0 - exp(l0 + (double)h * (l1 - l0) / 7.0);
}

// ================= tf32 tensor-core GEMM =================
// C[M,512] = X[M,512] @ W[512,512]^T + b, fused epilogue.
// BM=128, BN=64, BK=32; 256 threads = 8 warps (4m x 2n), warp tile 32x32.
// Smem layout: row stride 40 words; k within each 8-block permuted so that
// (k, k+4) are adjacent -> all fragment reads are conflict-free uint2 LDS.

__device__ __forceinline__ uint32_t f2tf32(float x) {
    uint32_t u;
    asm("cvt.rna.tf32.f32 %0, %1;" : "=r"(u) : "f"(x));
    return u;
}

__device__ __forceinline__ void mma_tf32(float d[4],
    uint32_t a0, uint32_t a1, uint32_t a2, uint32_t a3,
    uint32_t b0, uint32_t b1)
{
    asm volatile(
        "mma.sync.aligned.m16n8k8.row.col.f32.tf32.tf32.f32 "
        "{%0,%1,%2,%3}, {%4,%5,%6,%7}, {%8,%9}, {%0,%1,%2,%3};"
        : "+f"(d[0]), "+f"(d[1]), "+f"(d[2]), "+f"(d[3])
        : "r"(a0), "r"(a1), "r"(a2), "r"(a3), "r"(b0), "r"(b1));
}

__device__ __forceinline__ void epi_pair(float& v0, float& v1, int row, int col,
                                         const float* __restrict__ bias, int mode)
{
    v0 += bias[col];
    v1 += bias[col + 1];
    if (mode == 1 || mode == 2) {
        int n = row & (SEQ - 1);
        int d = col & 63;
        float s = g_sin[n*32 + (d >> 1)];
        float c = g_cos[n*32 + (d >> 1)];
        float e = v0, o = v1;
        v0 = e*c - o*s;
        v1 = o*c + e*s;
        if (mode == 2) { v0 *= 0.125f; v1 *= 0.125f; }
    } else if (mode == 3) {
        v0 = v0 / (1.f + expf(-v0));
        v1 = v1 / (1.f + expf(-v1));
    }
}

__device__ __forceinline__ void gemm_tc(
    const float* __restrict__ X, const float* __restrict__ W,
    const float* __restrict__ bias, float* __restrict__ C, int mode)
{
    __shared__ uint32_t As[128 * 40];
    __shared__ uint32_t Bs[64 * 40];

    const int tid  = threadIdx.x;
    const int lane = tid & 31;
    const int warp = tid >> 5;
    const int wm   = (warp >> 1) * 32;   // warp m-offset (0..96)
    const int wn   = (warp & 1) * 32;    // warp n-offset (0 or 32)
    const int lr   = lane >> 2;          // 0..7
    const int lc   = lane & 3;           // 0..3
    const int m0   = blockIdx.y * 128;
    const int n0   = blockIdx.x * 64;

    // global-load assignment: 32 rows x 8 float4-cols per pass
    const int r = tid >> 3;              // 0..31
    const int g = tid & 7;               // 0..7
    const int scol = 8 * (g >> 1) + (g & 1);  // permuted smem col base
    const float* Xp = X + (size_t)(m0 + r) * EMB + g * 4;
    const float* Wp = W + (size_t)(n0 + r) * EMB + g * 4;

    float4 ra[4], rb[2];
    float d[2][4][4];
    #pragma unroll
    for (int mi = 0; mi < 2; mi++)
        #pragma unroll
        for (int ni = 0; ni < 4; ni++)
            #pragma unroll
            for (int e = 0; e < 4; e++) d[mi][ni][e] = 0.f;

    #pragma unroll
    for (int p = 0; p < 4; p++) ra[p] = *(const float4*)(Xp + (size_t)p * 32 * EMB);
    #pragma unroll
    for (int p = 0; p < 2; p++) rb[p] = *(const float4*)(Wp + (size_t)p * 32 * EMB);

    for (int kt = 0; kt < 16; kt++) {
        // store staged tile to smem (convert to tf32)
        #pragma unroll
        for (int p = 0; p < 4; p++) {
            uint32_t* dst = &As[(r + 32*p) * 40 + scol];
            dst[0] = f2tf32(ra[p].x); dst[2] = f2tf32(ra[p].y);
            dst[4] = f2tf32(ra[p].z); dst[6] = f2tf32(ra[p].w);
        }
        #pragma unroll
        for (int p = 0; p < 2; p++) {
            uint32_t* dst = &Bs[(r + 32*p) * 40 + scol];
            dst[0] = f2tf32(rb[p].x); dst[2] = f2tf32(rb[p].y);
            dst[4] = f2tf32(rb[p].z); dst[6] = f2tf32(rb[p].w);
        }
        __syncthreads();

        if (kt < 15) {
            int k0 = (kt + 1) * 32;
            #pragma unroll
            for (int p = 0; p < 4; p++) ra[p] = *(const float4*)(Xp + k0 + (size_t)p * 32 * EMB);
            #pragma unroll
            for (int p = 0; p < 2; p++) rb[p] = *(const float4*)(Wp + k0 + (size_t)p * 32 * EMB);
        }

        #pragma unroll
        for (int ks = 0; ks < 4; ks++) {
            const int kcol = 8*ks + 2*lc;
            uint2 a_lo[2], a_hi[2], bf[4];
            #pragma unroll
            for (int mi = 0; mi < 2; mi++) {
                a_lo[mi] = *(const uint2*)&As[(wm + mi*16 + lr)     * 40 + kcol];
                a_hi[mi] = *(const uint2*)&As[(wm + mi*16 + 8 + lr) * 40 + kcol];
            }
            #pragma unroll
            for (int ni = 0; ni < 4; ni++)
                bf[ni] = *(const uint2*)&Bs[(wn + ni*8 + lr) * 40 + kcol];
            #pragma unroll
            for (int mi = 0; mi < 2; mi++)
                #pragma unroll
                for (int ni = 0; ni < 4; ni++)
                    mma_tf32(d[mi][ni], a_lo[mi].x, a_hi[mi].x, a_lo[mi].y, a_hi[mi].y,
                             bf[ni].x, bf[ni].y);
        }
        __syncthreads();
    }

    // epilogue: C fragment rows lr / lr+8, col pairs 2*lc (even/odd adjacent)
    #pragma unroll
    for (int mi = 0; mi < 2; mi++) {
        int row0 = m0 + wm + mi*16 + lr;
        #pragma unroll
        for (int ni = 0; ni < 4; ni++) {
            int col = n0 + wn + ni*8 + 2*lc;
            float v0 = d[mi][ni][0], v1 = d[mi][ni][1];
            epi_pair(v0, v1, row0, col, bias, mode);
            *(float2*)&C[(size_t)row0 * EMB + col] = make_float2(v0, v1);
            float v2 = d[mi][ni][2], v3 = d[mi][ni][3];
            epi_pair(v2, v3, row0 + 8, col, bias, mode);
            *(float2*)&C[(size_t)(row0 + 8) * EMB + col] = make_float2(v2, v3);
        }
    }
}

__global__ void __launch_bounds__(256) proj_kernel(
    const float* __restrict__ q_in, const float* __restrict__ k_in,
    const float* __restrict__ v_in,
    const float* __restrict__ Wq, const float* __restrict__ bq,
    const float* __restrict__ Wk, const float* __restrict__ bk,
    const float* __restrict__ Wv, const float* __restrict__ bv,
    const float* __restrict__ Wg, const float* __restrict__ bg)
{
    int job = blockIdx.z;
    const float* X; const float* W; const float* B; float* O; int mode;
    if      (job == 0) { X = q_in; W = Wq; B = bq; O = g_Q; mode = 1; }
    else if (job == 1) { X = k_in; W = Wk; B = bk; O = g_K; mode = 2; }
    else if (job == 2) { X = v_in; W = Wv; B = bv; O = g_V; mode = 0; }
    else               { X = q_in; W = Wg; B = bg; O = g_G; mode = 3; }
    gemm_tc(X, W, B, O, mode);
}

__global__ void __launch_bounds__(256) out_kernel(
    const float* __restrict__ Wo, const float* __restrict__ bo,
    float* __restrict__ out)
{
    gemm_tc(g_X2, Wo, bo, out, 0);
}

// ================= chunkwise retention =================
// R1: per-chunk A = (K * gamma^(C-j))^T V   [64 x 64]
__global__ void __launch_bounds__(256) chunk_kv_kernel()
{
    __shared__ float Ks[CHUNK * HDIM];
    __shared__ float Vs[CHUNK * HDIM];

    const int tid = threadIdx.x;
    const int tx  = tid & 15;
    const int ty  = tid >> 4;
    const int c   = blockIdx.x;
    const int h   = blockIdx.y;
    const int b   = blockIdx.z;
    const int rowbase = b * SEQ + c * CHUNK;
    const int coff    = h * HDIM;

    const double gd = head_gamma(h);
    const float  lg = (float)log(gd);

    for (int f = tid; f < CHUNK * 16; f += 256) {
        int s  = f >> 4;
        int d4 = f & 15;
        size_t gidx = (size_t)(rowbase + s) * EMB + coff + d4*4;
        float sc = expf(lg * (float)(CHUNK - s));
        float4 kv = *(const float4*)&g_K[gidx];
        kv.x *= sc; kv.y *= sc; kv.z *= sc; kv.w *= sc;
        *(float4*)&Ks[s*HDIM + d4*4] = kv;
        *(float4*)&Vs[s*HDIM + d4*4] = *(const float4*)&g_V[gidx];
    }
    __syncthreads();

    float acc[4][4];
    #pragma unroll
    for (int i = 0; i < 4; i++)
        #pragma unroll
        for (int j = 0; j < 4; j++) acc[i][j] = 0.f;

    #pragma unroll 8
    for (int s = 0; s < CHUNK; s++) {
        float4 a = *(const float4*)&Ks[s*HDIM + ty*4];
        float4 bb = *(const float4*)&Vs[s*HDIM + tx*4];
        float av[4] = {a.x, a.y, a.z, a.w};
        float bv[4] = {bb.x, bb.y, bb.z, bb.w};
        #pragma unroll
        for (int i = 0; i < 4; i++)
            #pragma unroll
            for (int j = 0; j < 4; j++)
                acc[i][j] = fmaf(av[i], bv[j], acc[i][j]);
    }

    float* Ap = g_A + (size_t)(((b*HEADS + h)*NCH + c) * HDIM * HDIM);
    #pragma unroll
    for (int i = 0; i < 4; i++)
        *(float4*)&Ap[(ty*4+i)*HDIM + tx*4] =
            make_float4(acc[i][0], acc[i][1], acc[i][2], acc[i][3]);
}

// R2: S_t = gamma^C * S_{t-1} + A_{t-1}.  Register-buffered: all 32 loads
// issued independently (MLP=32), then scan in regs, then 32 stores.
__global__ void __launch_bounds__(256) state_scan_kernel()
{
    const int bh  = blockIdx.x;
    const int seg = blockIdx.y;
    const int e   = seg * 256 + threadIdx.x;
    const int h   = bh & (HEADS - 1);
    const float gc = (float)pow(head_gamma(h), (double)CHUNK);

    const size_t base = (size_t)bh * NCH * HDIM * HDIM + e;
    float a[NCH];
    #pragma unroll
    for (int t = 0; t < NCH; t++)
        a[t] = g_A[base + (size_t)t * HDIM * HDIM];

    float s = 0.f;
    #pragma unroll
    for (int t = 0; t < NCH; t++) {
        g_S[base + (size_t)t * HDIM * HDIM] = s;
        s = gc * s + a[t];
    }
}

// R3: intra-chunk (diagonal decay tile) + cross term via state, fused GroupNorm*gate.
__global__ void __launch_bounds__(256) retention_kernel()
{
    __shared__ float QsT[HDIM * CHUNK];  // [d][q]
    __shared__ float KsT[HDIM * CHUNK];  // [d][s] -> S^T [s][q] -> O [q][d]
    __shared__ float Vs [CHUNK * HDIM];  // [s][d]
    __shared__ float Ss [HDIM * HDIM];   // state [dk][dv]

    const int tid = threadIdx.x;
    const int tx  = tid & 15;
    const int ty  = tid >> 4;
    const int c   = blockIdx.x;
    const int h   = blockIdx.y;
    const int b   = blockIdx.z;
    const int rowbase = b * SEQ + c * CHUNK;
    const int coff    = h * HDIM;

    const double gd = head_gamma(h);
    const float  gamma = (float)gd;
    const float  lg    = (float)log(gd);
    float gi[4], gjv[4];
    gi[0]  = 1.f; gi[1] = gamma; gi[2] = gamma*gamma; gi[3] = gi[2]*gamma;
    float ginv = 1.f / gamma;
    gjv[0] = 1.f; gjv[1] = ginv; gjv[2] = ginv*ginv;  gjv[3] = gjv[2]*ginv;

    const float* Sp = g_S + (size_t)(((b*HEADS + h)*NCH + c) * HDIM * HDIM);
    for (int f = tid; f < CHUNK * 16; f += 256) {
        int s  = f & 63;
        int d4 = f >> 6;
        size_t gidx = (size_t)(rowbase + s) * EMB + coff + d4*4;
        float4 qv = *(const float4*)&g_Q[gidx];
        QsT[(d4*4+0)*CHUNK + s] = qv.x;
        QsT[(d4*4+1)*CHUNK + s] = qv.y;
        QsT[(d4*4+2)*CHUNK + s] = qv.z;
        QsT[(d4*4+3)*CHUNK + s] = qv.w;
        float4 kv = *(const float4*)&g_K[gidx];
        KsT[(d4*4+0)*CHUNK + s] = kv.x;
        KsT[(d4*4+1)*CHUNK + s] = kv.y;
        KsT[(d4*4+2)*CHUNK + s] = kv.z;
        KsT[(d4*4+3)*CHUNK + s] = kv.w;
        *(float4*)&Vs[s*HDIM + d4*4] = *(const float4*)&g_V[gidx];
        *(float4*)&Ss[f*4] = *(const float4*)&Sp[f*4];
    }
    __syncthreads();

    // GEMM1 (intra): S[q][s] with decay + causal mask
    float sacc[4][4];
    #pragma unroll
    for (int i = 0; i < 4; i++)
        #pragma unroll
        for (int j = 0; j < 4; j++) sacc[i][j] = 0.f;
    #pragma unroll 8
    for (int d = 0; d < HDIM; d++) {
        float4 a  = *(const float4*)&QsT[d*CHUNK + ty*4];
        float4 bb = *(const float4*)&KsT[d*CHUNK + tx*4];
        float av[4] = {a.x, a.y, a.z, a.w};
        float bv[4] = {bb.x, bb.y, bb.z, bb.w};
        #pragma unroll
        for (int i = 0; i < 4; i++)
            #pragma unroll
            for (int j = 0; j < 4; j++)
                sacc[i][j] = fmaf(av[i], bv[j], sacc[i][j]);
    }
    {
        float d0 = expf(lg * (float)(ty*4 - tx*4));
        #pragma unroll
        for (int i = 0; i < 4; i++) {
            int n = ty*4 + i;
            #pragma unroll
            for (int j = 0; j < 4; j++) {
                int s = tx*4 + j;
                sacc[i][j] = (s <= n) ? sacc[i][j] * d0 * gi[i] * gjv[j] : 0.f;
            }
        }
    }
    __syncthreads();
    #pragma unroll
    for (int j = 0; j < 4; j++)
        *(float4*)&KsT[(tx*4+j)*CHUNK + ty*4] =
            make_float4(sacc[0][j], sacc[1][j], sacc[2][j], sacc[3][j]);
    __syncthreads();

    // GEMM2: O[q][d] = sum_s SsT[s][q] * Vs[s][d]
    float oacc[4][4];
    #pragma unroll
    for (int i = 0; i < 4; i++)
        #pragma unroll
        for (int j = 0; j < 4; j++) oacc[i][j] = 0.f;
    #pragma unroll 8
    for (int s = 0; s < CHUNK; s++) {
        float4 a  = *(const float4*)&KsT[s*CHUNK + ty*4];
        float4 bb = *(const float4*)&Vs[s*HDIM + tx*4];
        float av[4] = {a.x, a.y, a.z, a.w};
        float bv[4] = {bb.x, bb.y, bb.z, bb.w};
        #pragma unroll
        for (int i = 0; i < 4; i++)
            #pragma unroll
            for (int j = 0; j < 4; j++)
                oacc[i][j] = fmaf(av[i], bv[j], oacc[i][j]);
    }

    // GEMM3 (cross): O[q=i][dv] += gamma^i * sum_dk Q[i][dk] * S[dk][dv]
    {
        float cacc[4][4];
        #pragma unroll
        for (int i = 0; i < 4; i++)
            #pragma unroll
            for (int j = 0; j < 4; j++) cacc[i][j] = 0.f;
        #pragma unroll 8
        for (int d = 0; d < HDIM; d++) {
            float4 a  = *(const float4*)&QsT[d*CHUNK + ty*4];
            float4 bb = *(const float4*)&Ss[d*HDIM + tx*4];
            float av[4] = {a.x, a.y, a.z, a.w};
            float bv[4] = {bb.x, bb.y, bb.z, bb.w};
            #pragma unroll
            for (int i = 0; i < 4; i++)
                #pragma unroll
                for (int j = 0; j < 4; j++)
                    cacc[i][j] = fmaf(av[i], bv[j], cacc[i][j]);
        }
        #pragma unroll
        for (int i = 0; i < 4; i++) {
            float gq = expf(lg * (float)(ty*4 + i));
            #pragma unroll
            for (int j = 0; j < 4; j++)
                oacc[i][j] = fmaf(gq, cacc[i][j], oacc[i][j]);
        }
    }

    __syncthreads();
    #pragma unroll
    for (int i = 0; i < 4; i++)
        *(float4*)&KsT[(ty*4+i)*HDIM + tx*4] =
            make_float4(oacc[i][0], oacc[i][1], oacc[i][2], oacc[i][3]);
    __syncthreads();

    // GroupNorm over d (per q row) + SiLU-gate multiply; 4 threads per row
    const int r = tid >> 2;
    const int p = tid & 3;
    float vals[16];
    float lsum = 0.f;
    #pragma unroll
    for (int j = 0; j < 16; j++) {
        vals[j] = KsT[r*HDIM + p*16 + j];
        lsum += vals[j];
    }
    lsum += __shfl_xor_sync(0xffffffffu, lsum, 1);
    lsum += __shfl_xor_sync(0xffffffffu, lsum, 2);
    float mean = lsum * (1.f / 64.f);
    float lsq = 0.f;
    #pragma unroll
    for (int j = 0; j < 16; j++) {
        float dd = vals[j] - mean;
        lsq += dd * dd;
    }
    lsq += __shfl_xor_sync(0xffffffffu, lsq, 1);
    lsq += __shfl_xor_sync(0xffffffffu, lsq, 2);
    float rstd = rsqrtf(lsq * (1.f / 64.f) + 1e-6f);

    const int n = c * CHUNK + r;
    const size_t gidx = (size_t)(b * SEQ + n) * EMB + coff + p*16;
    #pragma unroll
    for (int j = 0; j < 16; j += 4) {
        float4 gte = *(const float4*)&g_G[gidx + j];
        float4 o;
        o.x = (vals[j+0] - mean) * rstd * gte.x;
        o.y = (vals[j+1] - mean) * rstd * gte.y;
        o.z = (vals[j+2] - mean) * rstd * gte.z;
        o.w = (vals[j+3] - mean) * rstd * gte.w;
        *(float4*)&g_X2[gidx + j] = o;
    }
}

// ---------------- launch ----------------
extern "C" void kernel_launch(void* const* d_in, const int* in_sizes, int n_in,
                              void* d_out, int out_size)
{
    const float* query = (const float*)d_in[0];
    const float* kk    = (const float*)d_in[1];
    const float* vv    = (const float*)d_in[2];
    const float* Wq    = (const float*)d_in[3];
    const float* bq    = (const float*)d_in[4];
    const float* Wk    = (const float*)d_in[5];
    const float* bk    = (const float*)d_in[6];
    const float* Wv    = (const float*)d_in[7];
    const float* bv    = (const float*)d_in[8];
    const float* Wg    = (const float*)d_in[9];
    const float* bg    = (const float*)d_in[10];
    const float* Wo    = (const float*)d_in[11];
    const float* bo    = (const float*)d_in[12];
    float* out = (float*)d_out;

    rotary_table_kernel<<<(SEQ*32 + 255) / 256, 256>>>();

    dim3 pg(8, 32, 4);              // n-tiles(64), m-tiles(128), jobs(Q,K,V,G)
    proj_kernel<<<pg, 256>>>(query, kk, vv, Wq, bq, Wk, bk, Wv, bv, Wg, bg);

    dim3 ag(NCH, HEADS, BATCH);     // per-chunk K'^T V
    chunk_kv_kernel<<<ag, 256>>>();

    dim3 sg(NBH, 16);               // state scan
    state_scan_kernel<<<sg, 256>>>();

    dim3 rg(NCH, HEADS, BATCH);     // intra + cross + GN + gate
    retention_kernel<<<rg, 256>>>();

    dim3 og(8, 32, 1);
    out_kernel<<<og, 256>>>(Wo, bo, out);
}